// round 5
// baseline (speedup 1.0000x reference)
#include <cuda_runtime.h>
#include <math.h>
#include <stdint.h>

// ---------------- scratch ----------------
#define NROWS 8192
#define DV    512
__device__ float g_Qp[NROWS * DV];
__device__ float g_Kp[NROWS * DV];
__device__ float g_Vp[NROWS * DV];
__device__ float g_O [NROWS * DV];
__device__ float g_X [NROWS * DV];
__device__ float g_T [NROWS * DV];

// ---------------- helpers ----------------
__device__ __forceinline__ unsigned f2tf(float x) {
    unsigned r; asm("cvt.rna.tf32.f32 %0, %1;" : "=r"(r) : "f"(x)); return r;
}
__device__ __forceinline__ float round_tf(float x) { return __uint_as_float(f2tf(x)); }

__device__ __forceinline__ void mma8(float* d, const unsigned* a, const unsigned* b) {
    asm volatile(
        "mma.sync.aligned.m16n8k8.row.col.f32.tf32.tf32.f32 "
        "{%0,%1,%2,%3},{%4,%5,%6,%7},{%8,%9},{%0,%1,%2,%3};"
        : "+f"(d[0]), "+f"(d[1]), "+f"(d[2]), "+f"(d[3])
        : "r"(a[0]), "r"(a[1]), "r"(a[2]), "r"(a[3]), "r"(b[0]), "r"(b[1]));
}
__device__ __forceinline__ void cpa16(uint32_t s, const void* g) {
    asm volatile("cp.async.cg.shared.global [%0], [%1], 16;" :: "r"(s), "l"(g));
}
#define CPA_COMMIT() asm volatile("cp.async.commit_group;")
#define CPA_WAIT(n)  asm volatile("cp.async.wait_group %0;" :: "n"(n))

// ---------------- tf32 GEMM with cp.async double buffering ----------------
// C[M,N] = A[M,K] @ W[N,K]^T + bias. mode 0: store rna-rounded. mode 1: relu+residual(A), plain store.
#define GP 20
__global__ __launch_bounds__(256)
void gemm_tf32(const float* __restrict__ A, const float* __restrict__ W,
               const float* __restrict__ bias, float* __restrict__ C,
               int M, int N, int K, int mode)
{
    __shared__ float As[2][128 * GP];
    __shared__ float Bs[2][128 * GP];

    const int tid  = threadIdx.x;
    const int lane = tid & 31;
    const int warp = tid >> 5;
    const int wm = warp & 3;
    const int wn = warp >> 2;
    const int bm = blockIdx.y * 128;
    const int bn = blockIdx.x * 128;
    const int g4 = lane >> 2;
    const int t4 = lane & 3;

    float acc[2][8][4];
#pragma unroll
    for (int mi = 0; mi < 2; mi++)
#pragma unroll
        for (int ni = 0; ni < 8; ni++)
#pragma unroll
            for (int j = 0; j < 4; j++) acc[mi][ni][j] = 0.f;

    auto issue = [&](int k0, int buf) {
#pragma unroll
        for (int i = 0; i < 2; i++) {
            const int cid = i * 256 + tid;          // 0..511
            const int row = cid >> 2;
            const int c4  = (cid & 3) * 4;
            cpa16((uint32_t)__cvta_generic_to_shared(&As[buf][row * GP + c4]),
                  &A[(size_t)(bm + row) * K + k0 + c4]);
            cpa16((uint32_t)__cvta_generic_to_shared(&Bs[buf][row * GP + c4]),
                  &W[(size_t)(bn + row) * K + k0 + c4]);
        }
    };

    const int NIT = K / 16;
    issue(0, 0); CPA_COMMIT();

    for (int it = 0; it < NIT; it++) {
        const int buf = it & 1;
        if (it + 1 < NIT) { issue((it + 1) * 16, buf ^ 1); CPA_COMMIT(); CPA_WAIT(1); }
        else              { CPA_WAIT(0); }
        __syncthreads();

#pragma unroll
        for (int ks = 0; ks < 2; ks++) {
            unsigned af[2][4];
#pragma unroll
            for (int mi = 0; mi < 2; mi++) {
                const int r = wm * 32 + mi * 16 + g4;
                const int c = ks * 8 + t4;
                af[mi][0] = __float_as_uint(As[buf][r * GP + c]);
                af[mi][1] = __float_as_uint(As[buf][(r + 8) * GP + c]);
                af[mi][2] = __float_as_uint(As[buf][r * GP + c + 4]);
                af[mi][3] = __float_as_uint(As[buf][(r + 8) * GP + c + 4]);
            }
#pragma unroll
            for (int ni = 0; ni < 8; ni++) {
                unsigned bf[2];
                const int n = wn * 64 + ni * 8 + g4;
                const int c = ks * 8 + t4;
                bf[0] = __float_as_uint(Bs[buf][n * GP + c]);
                bf[1] = __float_as_uint(Bs[buf][n * GP + c + 4]);
                mma8(acc[0][ni], af[0], bf);
                mma8(acc[1][ni], af[1], bf);
            }
        }
        __syncthreads();
    }

#pragma unroll
    for (int mi = 0; mi < 2; mi++) {
#pragma unroll
        for (int ni = 0; ni < 8; ni++) {
            const int row = bm + wm * 32 + mi * 16 + g4;
            const int col = bn + wn * 64 + ni * 8 + 2 * t4;
            const float b0 = bias[col], b1 = bias[col + 1];
            float v00 = acc[mi][ni][0] + b0, v01 = acc[mi][ni][1] + b1;
            float v10 = acc[mi][ni][2] + b0, v11 = acc[mi][ni][3] + b1;
            if (mode == 1) {
                v00 = fmaxf(v00, 0.f) + A[(size_t)row * K + col];
                v01 = fmaxf(v01, 0.f) + A[(size_t)row * K + col + 1];
                v10 = fmaxf(v10, 0.f) + A[(size_t)(row + 8) * K + col];
                v11 = fmaxf(v11, 0.f) + A[(size_t)(row + 8) * K + col + 1];
            } else {
                v00 = round_tf(v00); v01 = round_tf(v01);
                v10 = round_tf(v10); v11 = round_tf(v11);
            }
            *(float2*)&C[(size_t)row * N + col]       = make_float2(v00, v01);
            *(float2*)&C[(size_t)(row + 8) * N + col] = make_float2(v10, v11);
        }
    }
}

// ---------------- flash attention: mma.sync tf32, cp.async double buffer, no-max softmax ----------------
// 256 threads = 8 warps; block = (128 q-rows, head, batch); warp owns 16 q rows.
#define KS 68   // stride for K and P tiles (g4-indexed rows -> conflict-free)
#define VS 72   // stride for V tile (t4-indexed rows -> conflict-free)
__global__ __launch_bounds__(256, 2)
void attn_mma2(const float* __restrict__ Qp, const float* __restrict__ Kp,
               const float* __restrict__ Vp, float* __restrict__ O)
{
    extern __shared__ float dsm[];
    float* K0 = dsm;
    float* K1 = K0 + 64 * KS;
    float* V0 = K1 + 64 * KS;
    float* V1 = V0 + 64 * VS;
    float* Ps = V1 + 64 * VS;
    float* Kb2[2] = {K0, K1};
    float* Vb2[2] = {V0, V1};

    const int tid  = threadIdx.x;
    const int lane = tid & 31;
    const int warp = tid >> 5;
    const int g4 = lane >> 2;
    const int t4 = lane & 3;

    const int qt = blockIdx.x, h = blockIdx.y, b = blockIdx.z;
    const int q0 = qt * 128;
    const size_t gbase = ((size_t)b * 1024) * 512 + (size_t)h * 64;
    const float scale = 0.044194173824159216f;  // 1/sqrt(512)

    auto issue = [&](int kt, int bufi) {
        float* kd = Kb2[bufi];
        float* vd = Vb2[bufi];
#pragma unroll
        for (int i = 0; i < 4; i++) {
            const int cid = i * 256 + tid;     // 0..1023
            const int row = cid >> 4;
            const int c4  = (cid & 15) * 4;
            const size_t goff = gbase + (size_t)(kt * 64 + row) * 512 + c4;
            cpa16((uint32_t)__cvta_generic_to_shared(&kd[row * KS + c4]), Kp + goff);
            cpa16((uint32_t)__cvta_generic_to_shared(&vd[row * VS + c4]), Vp + goff);
        }
    };

    // Q fragments (rna tf32, pre-scaled), register-resident
    const int qr = q0 + warp * 16 + g4;
    const float* Qrow0 = Qp + gbase + (size_t)qr * 512;
    const float* Qrow1 = Qrow0 + (size_t)8 * 512;
    unsigned aq[8][4];
#pragma unroll
    for (int ks = 0; ks < 8; ks++) {
        const int c = ks * 8 + t4;
        aq[ks][0] = f2tf(Qrow0[c] * scale);
        aq[ks][1] = f2tf(Qrow1[c] * scale);
        aq[ks][2] = f2tf(Qrow0[c + 4] * scale);
        aq[ks][3] = f2tf(Qrow1[c + 4] * scale);
    }

    float l0 = 0.f, l1 = 0.f;
    float o[8][4];
#pragma unroll
    for (int ni = 0; ni < 8; ni++)
#pragma unroll
        for (int j = 0; j < 4; j++) o[ni][j] = 0.f;

    issue(0, 0); CPA_COMMIT();

    const int pr = warp * 16 + g4;

    for (int kt = 0; kt < 16; kt++) {
        const int buf = kt & 1;
        if (kt < 15) { issue(kt + 1, buf ^ 1); CPA_COMMIT(); CPA_WAIT(1); }
        else         { CPA_WAIT(0); }
        __syncthreads();

        const float* Kt = Kb2[buf];
        const float* Vt = Vb2[buf];

        // S = Qs @ K^T (16 rows x 64 keys per warp)
        float s[8][4];
#pragma unroll
        for (int ni = 0; ni < 8; ni++)
#pragma unroll
            for (int j = 0; j < 4; j++) s[ni][j] = 0.f;

#pragma unroll
        for (int ks = 0; ks < 8; ks++) {
#pragma unroll
            for (int ni = 0; ni < 8; ni++) {
                unsigned bf[2];
                const int n = ni * 8 + g4;
                const int c = ks * 8 + t4;
                bf[0] = __float_as_uint(Kt[n * KS + c]);
                bf[1] = __float_as_uint(Kt[n * KS + c + 4]);
                mma8(s[ni], aq[ks], bf);
            }
        }

        // softmax without max subtraction (scores bounded; clamp for safety).
        // NOTE: each thread sees only keys {ni*8+2*t4, +1}; l reduced across t4 lanes AFTER the loop.
        float rs0 = 0.f, rs1 = 0.f;
#pragma unroll
        for (int ni = 0; ni < 8; ni++) {
            s[ni][0] = __expf(fminf(s[ni][0], 60.f)); rs0 += s[ni][0];
            s[ni][1] = __expf(fminf(s[ni][1], 60.f)); rs0 += s[ni][1];
            s[ni][2] = __expf(fminf(s[ni][2], 60.f)); rs1 += s[ni][2];
            s[ni][3] = __expf(fminf(s[ni][3], 60.f)); rs1 += s[ni][3];
        }
        l0 += rs0; l1 += rs1;

        // P -> smem (warp-private rows), raw fp32 (mma truncates)
#pragma unroll
        for (int ni = 0; ni < 8; ni++) {
            const int col = ni * 8 + 2 * t4;
            *(float2*)&Ps[pr * KS + col]       = make_float2(s[ni][0], s[ni][1]);
            *(float2*)&Ps[(pr + 8) * KS + col] = make_float2(s[ni][2], s[ni][3]);
        }
        __syncwarp();

        // O += P @ V
#pragma unroll
        for (int ks = 0; ks < 8; ks++) {
            unsigned ap[4];
            const int c = ks * 8 + t4;
            ap[0] = __float_as_uint(Ps[pr * KS + c]);
            ap[1] = __float_as_uint(Ps[(pr + 8) * KS + c]);
            ap[2] = __float_as_uint(Ps[pr * KS + c + 4]);
            ap[3] = __float_as_uint(Ps[(pr + 8) * KS + c + 4]);
#pragma unroll
            for (int ni = 0; ni < 8; ni++) {
                unsigned bf[2];
                bf[0] = __float_as_uint(Vt[(ks * 8 + t4) * VS + ni * 8 + g4]);
                bf[1] = __float_as_uint(Vt[(ks * 8 + t4 + 4) * VS + ni * 8 + g4]);
                mma8(o[ni], ap, bf);
            }
        }
        __syncthreads();
    }

    // reduce softmax denominators across the 4 t4-lanes (full 1024-key sums)
    l0 += __shfl_xor_sync(0xffffffffu, l0, 1);
    l0 += __shfl_xor_sync(0xffffffffu, l0, 2);
    l1 += __shfl_xor_sync(0xffffffffu, l1, 1);
    l1 += __shfl_xor_sync(0xffffffffu, l1, 2);

    // epilogue: normalize + Q residual
    const float inv0 = 1.f / l0, inv1 = 1.f / l1;
    float* Ob = O + gbase + (size_t)qr * 512;
#pragma unroll
    for (int ni = 0; ni < 8; ni++) {
        const int col = ni * 8 + 2 * t4;
        float2 r0 = make_float2(o[ni][0] * inv0 + Qrow0[col],
                                o[ni][1] * inv0 + Qrow0[col + 1]);
        float2 r1 = make_float2(o[ni][2] * inv1 + Qrow1[col],
                                o[ni][3] * inv1 + Qrow1[col + 1]);
        *(float2*)&Ob[col]                   = r0;
        *(float2*)&Ob[(size_t)8 * 512 + col] = r1;
    }
}

// ---------------- layernorm over 512 features ----------------
__global__ __launch_bounds__(128)
void ln512_kernel(const float* __restrict__ X, const float* __restrict__ g,
                  const float* __restrict__ beta, float* __restrict__ Y, int roundOut)
{
    const int row = blockIdx.x;
    const int tid = threadIdx.x;
    const int lane = tid & 31;
    const int wid = tid >> 5;

    float4 v = *(const float4*)&X[(size_t)row * 512 + tid * 4];
    float s  = v.x + v.y + v.z + v.w;
    float sq = v.x * v.x + v.y * v.y + v.z * v.z + v.w * v.w;
#pragma unroll
    for (int o = 16; o; o >>= 1) {
        s  += __shfl_xor_sync(0xffffffffu, s, o);
        sq += __shfl_xor_sync(0xffffffffu, sq, o);
    }
    __shared__ float ws[4], wq[4];
    if (lane == 0) { ws[wid] = s; wq[wid] = sq; }
    __syncthreads();
    float ts = ws[0] + ws[1] + ws[2] + ws[3];
    float tq = wq[0] + wq[1] + wq[2] + wq[3];
    const float mean = ts * (1.f / 512.f);
    const float var  = tq * (1.f / 512.f) - mean * mean;
    const float rstd = rsqrtf(var + 1e-5f);

    float4 gv = *(const float4*)&g[tid * 4];
    float4 bv = *(const float4*)&beta[tid * 4];
    float4 o;
    o.x = (v.x - mean) * rstd * gv.x + bv.x;
    o.y = (v.y - mean) * rstd * gv.y + bv.y;
    o.z = (v.z - mean) * rstd * gv.z + bv.z;
    o.w = (v.w - mean) * rstd * gv.w + bv.w;
    if (roundOut) {
        o.x = round_tf(o.x); o.y = round_tf(o.y);
        o.z = round_tf(o.z); o.w = round_tf(o.w);
    }
    *(float4*)&Y[(size_t)row * 512 + tid * 4] = o;
}

// ---------------- launch ----------------
extern "C" void kernel_launch(void* const* d_in, const int* in_sizes, int n_in,
                              void* d_out, int out_size)
{
    const float* Q   = (const float*)d_in[0];
    const float* K   = (const float*)d_in[1];
    const float* Wq  = (const float*)d_in[2];
    const float* bq  = (const float*)d_in[3];
    const float* Wk  = (const float*)d_in[4];
    const float* bk  = (const float*)d_in[5];
    const float* Wv  = (const float*)d_in[6];
    const float* bv  = (const float*)d_in[7];
    const float* Wo  = (const float*)d_in[8];
    const float* bo  = (const float*)d_in[9];
    const float* g0  = (const float*)d_in[10];
    const float* be0 = (const float*)d_in[11];
    const float* g1  = (const float*)d_in[12];
    const float* be1 = (const float*)d_in[13];
    float* out = (float*)d_out;

    float *Qp, *Kp, *Vp, *Obuf, *Xbuf, *Tbuf;
    cudaGetSymbolAddress((void**)&Qp,   g_Qp);
    cudaGetSymbolAddress((void**)&Kp,   g_Kp);
    cudaGetSymbolAddress((void**)&Vp,   g_Vp);
    cudaGetSymbolAddress((void**)&Obuf, g_O);
    cudaGetSymbolAddress((void**)&Xbuf, g_X);
    cudaGetSymbolAddress((void**)&Tbuf, g_T);

    const int SMEM_ATT = (2 * 64 * KS + 2 * 64 * VS + 128 * KS) * (int)sizeof(float); // 106496
    cudaFuncSetAttribute(attn_mma2, cudaFuncAttributeMaxDynamicSharedMemorySize, SMEM_ATT);

    dim3 gdim(DV / 128, NROWS / 128);   // (4, 64)
    gemm_tf32<<<gdim, 256>>>(Q, Wq, bq, Qp, NROWS, DV, 512, 0);
    gemm_tf32<<<gdim, 256>>>(K, Wk, bk, Kp, NROWS, DV, 512, 0);
    gemm_tf32<<<gdim, 256>>>(K, Wv, bv, Vp, NROWS, DV, 512, 0);

    dim3 adim(8, 8, 8);                 // (q-tiles of 128, heads, batch)
    attn_mma2<<<adim, 256, SMEM_ATT>>>(Qp, Kp, Vp, Obuf);

    ln512_kernel<<<NROWS, 128>>>(Obuf, g0, be0, Xbuf, 1);
    gemm_tf32<<<gdim, 256>>>(Xbuf, Wo, bo, Tbuf, NROWS, DV, 512, 1);
    ln512_kernel<<<NROWS, 128>>>(Tbuf, g1, be1, out, 0);
}

// round 6
// speedup vs baseline: 1.8784x; 1.8784x over previous
#include <cuda_runtime.h>
#include <math.h>
#include <stdint.h>

// ---------------- scratch ----------------
#define NROWS 8192
#define DV    512
__device__ float g_Qp[NROWS * DV];
__device__ float g_Kp[NROWS * DV];
__device__ float g_Vt[NROWS * DV];   // V projected, transposed: [b][h][d(64)][key(1024)]
__device__ float g_O [NROWS * DV];
__device__ float g_X [NROWS * DV];
__device__ float g_T [NROWS * DV];

// ---------------- helpers ----------------
__device__ __forceinline__ unsigned f2tf(float x) {
    unsigned r; asm("cvt.rna.tf32.f32 %0, %1;" : "=r"(r) : "f"(x)); return r;
}
__device__ __forceinline__ float round_tf(float x) { return __uint_as_float(f2tf(x)); }

__device__ __forceinline__ void mma8(float* d, const unsigned* a, const unsigned* b) {
    asm volatile(
        "mma.sync.aligned.m16n8k8.row.col.f32.tf32.tf32.f32 "
        "{%0,%1,%2,%3},{%4,%5,%6,%7},{%8,%9},{%0,%1,%2,%3};"
        : "+f"(d[0]), "+f"(d[1]), "+f"(d[2]), "+f"(d[3])
        : "r"(a[0]), "r"(a[1]), "r"(a[2]), "r"(a[3]), "r"(b[0]), "r"(b[1]));
}
__device__ __forceinline__ void ldsm4(unsigned& r0, unsigned& r1, unsigned& r2, unsigned& r3,
                                      uint32_t addr) {
    asm volatile("ldmatrix.sync.aligned.m8n8.x4.shared.b16 {%0,%1,%2,%3}, [%4];"
                 : "=r"(r0), "=r"(r1), "=r"(r2), "=r"(r3) : "r"(addr));
}
__device__ __forceinline__ void cpa16(uint32_t s, const void* g) {
    asm volatile("cp.async.cg.shared.global [%0], [%1], 16;" :: "r"(s), "l"(g));
}
#define CPA_COMMIT() asm volatile("cp.async.commit_group;")
#define CPA_WAIT(n)  asm volatile("cp.async.wait_group %0;" :: "n"(n))

// ---------------- tf32 GEMM, cp.async double buffer, ldmatrix operand feed ----------------
// C[M,N] = A[M,K] @ W[N,K]^T + bias.
// mode 0: store rna-rounded. mode 1: relu+residual(A). mode 2: store transposed (Vt layout).
#define GP 20
__global__ __launch_bounds__(256)
void gemm_tf32(const float* __restrict__ A, const float* __restrict__ W,
               const float* __restrict__ bias, float* __restrict__ C,
               int M, int N, int K, int mode)
{
    __shared__ __align__(16) float As[2][128 * GP];
    __shared__ __align__(16) float Bs[2][128 * GP];

    const int tid  = threadIdx.x;
    const int lane = tid & 31;
    const int warp = tid >> 5;
    const int wm = warp & 3;
    const int wn = warp >> 2;
    const int bm = blockIdx.y * 128;
    const int bn = blockIdx.x * 128;
    const int g4 = lane >> 2;
    const int t4 = lane & 3;

    // ldmatrix lane constants
    const int i8 = lane & 7;
    const uint32_t obA = (uint32_t)(((wm * 32 + ((lane >> 3) & 1) * 8 + i8) * GP
                                     + (lane >> 4) * 4) * 4);
    const uint32_t obB = (uint32_t)(((wn * 64 + (lane >> 4) * 8 + i8) * GP
                                     + ((lane >> 3) & 1) * 4) * 4);
    const uint32_t asu0 = (uint32_t)__cvta_generic_to_shared(&As[0][0]);
    const uint32_t asu1 = (uint32_t)__cvta_generic_to_shared(&As[1][0]);
    const uint32_t bsu0 = (uint32_t)__cvta_generic_to_shared(&Bs[0][0]);
    const uint32_t bsu1 = (uint32_t)__cvta_generic_to_shared(&Bs[1][0]);

    float acc[2][8][4];
#pragma unroll
    for (int mi = 0; mi < 2; mi++)
#pragma unroll
        for (int ni = 0; ni < 8; ni++)
#pragma unroll
            for (int j = 0; j < 4; j++) acc[mi][ni][j] = 0.f;

    auto issue = [&](int k0, int buf) {
#pragma unroll
        for (int i = 0; i < 2; i++) {
            const int cid = i * 256 + tid;          // 0..511
            const int row = cid >> 2;
            const int c4  = (cid & 3) * 4;
            cpa16((uint32_t)__cvta_generic_to_shared(&As[buf][row * GP + c4]),
                  &A[(size_t)(bm + row) * K + k0 + c4]);
            cpa16((uint32_t)__cvta_generic_to_shared(&Bs[buf][row * GP + c4]),
                  &W[(size_t)(bn + row) * K + k0 + c4]);
        }
    };

    const int NIT = K / 16;
    issue(0, 0); CPA_COMMIT();

    for (int it = 0; it < NIT; it++) {
        const int buf = it & 1;
        if (it + 1 < NIT) { issue((it + 1) * 16, buf ^ 1); CPA_COMMIT(); CPA_WAIT(1); }
        else              { CPA_WAIT(0); }
        __syncthreads();

        const uint32_t au = buf ? asu1 : asu0;
        const uint32_t bu = buf ? bsu1 : bsu0;
#pragma unroll
        for (int ks = 0; ks < 2; ks++) {
            unsigned af[2][4];
#pragma unroll
            for (int mi = 0; mi < 2; mi++)
                ldsm4(af[mi][0], af[mi][1], af[mi][2], af[mi][3],
                      au + obA + (uint32_t)((mi * 16 * GP + ks * 8) * 4));
#pragma unroll
            for (int n2 = 0; n2 < 4; n2++) {
                unsigned b0, b1, b2, b3;
                ldsm4(b0, b1, b2, b3, bu + obB + (uint32_t)((n2 * 16 * GP + ks * 8) * 4));
                unsigned be[2] = {b0, b1}, bo_[2] = {b2, b3};
                mma8(acc[0][n2 * 2],     af[0], be);
                mma8(acc[1][n2 * 2],     af[1], be);
                mma8(acc[0][n2 * 2 + 1], af[0], bo_);
                mma8(acc[1][n2 * 2 + 1], af[1], bo_);
            }
        }
        __syncthreads();
    }

#pragma unroll
    for (int mi = 0; mi < 2; mi++) {
#pragma unroll
        for (int ni = 0; ni < 8; ni++) {
            const int row = bm + wm * 32 + mi * 16 + g4;
            const int col = bn + wn * 64 + ni * 8 + 2 * t4;
            const float b0 = bias[col], b1 = bias[col + 1];
            float v00 = acc[mi][ni][0] + b0, v01 = acc[mi][ni][1] + b1;
            float v10 = acc[mi][ni][2] + b0, v11 = acc[mi][ni][3] + b1;
            if (mode == 1) {
                v00 = fmaxf(v00, 0.f) + A[(size_t)row * K + col];
                v01 = fmaxf(v01, 0.f) + A[(size_t)row * K + col + 1];
                v10 = fmaxf(v10, 0.f) + A[(size_t)(row + 8) * K + col];
                v11 = fmaxf(v11, 0.f) + A[(size_t)(row + 8) * K + col + 1];
            } else {
                v00 = round_tf(v00); v01 = round_tf(v01);
                v10 = round_tf(v10); v11 = round_tf(v11);
            }
            if (mode == 2) {
                // transposed store: Vt[((b*8+h)*64+d)*1024 + key]
                const int b_ = row >> 10, key = row & 1023;
                const int h_ = col >> 6, d_ = col & 63;
                float* base = C + (((size_t)(b_ * 8 + h_) * 64 + d_) << 10);
                base[key]            = v00;
                base[1024 + key]     = v01;   // d_+1
                base[key + 8]        = v10;
                base[1024 + key + 8] = v11;
            } else {
                *(float2*)&C[(size_t)row * N + col]       = make_float2(v00, v01);
                *(float2*)&C[(size_t)(row + 8) * N + col] = make_float2(v10, v11);
            }
        }
    }
}

// ---------------- flash attention: tf32 mma + ldmatrix feed + cp.async pipeline ----------------
// 256 threads = 8 warps; block = (128 q-rows, head, batch); warp owns 16 q rows.
#define KS 68   // tile stride (floats); rows land on distinct bank quads for ldmatrix
__global__ __launch_bounds__(256, 2)
void attn_mma3(const float* __restrict__ Qp, const float* __restrict__ Kp,
               const float* __restrict__ Vt, float* __restrict__ O)
{
    extern __shared__ __align__(16) float dsm[];
    float* K0 = dsm;                 // [64][KS]
    float* K1 = K0 + 64 * KS;
    float* V0 = K1 + 64 * KS;        // Vt tiles: [d(64)][key(64)]
    float* V1 = V0 + 64 * KS;
    float* Ps = V1 + 64 * KS;        // [128][KS]
    float* Kb2[2] = {K0, K1};
    float* Vb2[2] = {V0, V1};

    const int tid  = threadIdx.x;
    const int lane = tid & 31;
    const int warp = tid >> 5;
    const int g4 = lane >> 2;
    const int t4 = lane & 3;
    const int i8 = lane & 7;

    const int qt = blockIdx.x, h = blockIdx.y, b = blockIdx.z;
    const int q0 = qt * 128;
    const size_t gbase  = ((size_t)b * 1024) * 512 + (size_t)h * 64;
    const size_t vtbase = ((size_t)(b * 8 + h)) << 16;   // *64*1024
    const float scale = 0.044194173824159216f;  // 1/sqrt(512)

    // ldmatrix lane constants
    const uint32_t obB = (uint32_t)((((lane >> 4) * 8 + i8) * KS + ((lane >> 3) & 1) * 4) * 4);
    const uint32_t obA = (uint32_t)(((warp * 16 + ((lane >> 3) & 1) * 8 + i8) * KS
                                     + (lane >> 4) * 4) * 4);
    const uint32_t ku0 = (uint32_t)__cvta_generic_to_shared(K0);
    const uint32_t ku1 = (uint32_t)__cvta_generic_to_shared(K1);
    const uint32_t vu0 = (uint32_t)__cvta_generic_to_shared(V0);
    const uint32_t vu1 = (uint32_t)__cvta_generic_to_shared(V1);
    const uint32_t psu = (uint32_t)__cvta_generic_to_shared(Ps);

    auto issue = [&](int kt, int bufi) {
        float* kd = Kb2[bufi];
        float* vd = Vb2[bufi];
#pragma unroll
        for (int i = 0; i < 4; i++) {
            const int cid = i * 256 + tid;     // 0..1023
            const int row = cid >> 4;          // 0..63
            const int c4  = (cid & 15) * 4;    // 0..60
            cpa16((uint32_t)__cvta_generic_to_shared(&kd[row * KS + c4]),
                  Kp + gbase + (size_t)(kt * 64 + row) * 512 + c4);
            cpa16((uint32_t)__cvta_generic_to_shared(&vd[row * KS + c4]),
                  Vt + vtbase + (size_t)row * 1024 + kt * 64 + c4);
        }
    };

    // Q fragments (rna tf32, pre-scaled), register-resident
    const int qr = q0 + warp * 16 + g4;
    const float* Qrow0 = Qp + gbase + (size_t)qr * 512;
    const float* Qrow1 = Qrow0 + (size_t)8 * 512;
    unsigned aq[8][4];
#pragma unroll
    for (int ks = 0; ks < 8; ks++) {
        const int c = ks * 8 + t4;
        aq[ks][0] = f2tf(Qrow0[c] * scale);
        aq[ks][1] = f2tf(Qrow1[c] * scale);
        aq[ks][2] = f2tf(Qrow0[c + 4] * scale);
        aq[ks][3] = f2tf(Qrow1[c + 4] * scale);
    }

    float l0 = 0.f, l1 = 0.f;
    float o[8][4];
#pragma unroll
    for (int ni = 0; ni < 8; ni++)
#pragma unroll
        for (int j = 0; j < 4; j++) o[ni][j] = 0.f;

    issue(0, 0); CPA_COMMIT();

    const int pr = warp * 16 + g4;

    for (int kt = 0; kt < 16; kt++) {
        const int buf = kt & 1;
        if (kt < 15) { issue(kt + 1, buf ^ 1); CPA_COMMIT(); CPA_WAIT(1); }
        else         { CPA_WAIT(0); }
        __syncthreads();

        const uint32_t ku = buf ? ku1 : ku0;
        const uint32_t vu = buf ? vu1 : vu0;

        // S = Qs @ K^T (16 rows x 64 keys per warp), B fragments via ldmatrix
        float s[8][4];
#pragma unroll
        for (int ni = 0; ni < 8; ni++)
#pragma unroll
            for (int j = 0; j < 4; j++) s[ni][j] = 0.f;

#pragma unroll
        for (int ks = 0; ks < 8; ks++) {
#pragma unroll
            for (int n2 = 0; n2 < 4; n2++) {
                unsigned b0, b1, b2, b3;
                ldsm4(b0, b1, b2, b3, ku + obB + (uint32_t)((n2 * 16 * KS + ks * 8) * 4));
                unsigned be[2] = {b0, b1}, bo_[2] = {b2, b3};
                mma8(s[n2 * 2],     aq[ks], be);
                mma8(s[n2 * 2 + 1], aq[ks], bo_);
            }
        }

        // softmax without max subtraction (scores bounded; clamp for safety).
        // l holds partial sums (this thread's 16 keys); reduced across t4 lanes after loop.
        float rs0 = 0.f, rs1 = 0.f;
#pragma unroll
        for (int ni = 0; ni < 8; ni++) {
            s[ni][0] = __expf(fminf(s[ni][0], 60.f)); rs0 += s[ni][0];
            s[ni][1] = __expf(fminf(s[ni][1], 60.f)); rs0 += s[ni][1];
            s[ni][2] = __expf(fminf(s[ni][2], 60.f)); rs1 += s[ni][2];
            s[ni][3] = __expf(fminf(s[ni][3], 60.f)); rs1 += s[ni][3];
        }
        l0 += rs0; l1 += rs1;

        // P -> smem (warp-private rows)
#pragma unroll
        for (int ni = 0; ni < 8; ni++) {
            const int col = ni * 8 + 2 * t4;
            *(float2*)&Ps[pr * KS + col]       = make_float2(s[ni][0], s[ni][1]);
            *(float2*)&Ps[(pr + 8) * KS + col] = make_float2(s[ni][2], s[ni][3]);
        }
        __syncwarp();

        // O += P @ V ; A=P and B=Vt fragments via ldmatrix
#pragma unroll
        for (int ks = 0; ks < 8; ks++) {
            unsigned ap[4];
            ldsm4(ap[0], ap[1], ap[2], ap[3], psu + obA + (uint32_t)(ks * 8 * 4));
#pragma unroll
            for (int n2 = 0; n2 < 4; n2++) {
                unsigned b0, b1, b2, b3;
                ldsm4(b0, b1, b2, b3, vu + obB + (uint32_t)((n2 * 16 * KS + ks * 8) * 4));
                unsigned be[2] = {b0, b1}, bo_[2] = {b2, b3};
                mma8(o[n2 * 2],     ap, be);
                mma8(o[n2 * 2 + 1], ap, bo_);
            }
        }
        __syncthreads();
    }

    // reduce softmax denominators across the 4 t4-lanes (full 1024-key sums)
    l0 += __shfl_xor_sync(0xffffffffu, l0, 1);
    l0 += __shfl_xor_sync(0xffffffffu, l0, 2);
    l1 += __shfl_xor_sync(0xffffffffu, l1, 1);
    l1 += __shfl_xor_sync(0xffffffffu, l1, 2);

    // epilogue: normalize + Q residual
    const float inv0 = 1.f / l0, inv1 = 1.f / l1;
    float* Ob = O + gbase + (size_t)qr * 512;
#pragma unroll
    for (int ni = 0; ni < 8; ni++) {
        const int col = ni * 8 + 2 * t4;
        float2 r0 = make_float2(o[ni][0] * inv0 + Qrow0[col],
                                o[ni][1] * inv0 + Qrow0[col + 1]);
        float2 r1 = make_float2(o[ni][2] * inv1 + Qrow1[col],
                                o[ni][3] * inv1 + Qrow1[col + 1]);
        *(float2*)&Ob[col]                   = r0;
        *(float2*)&Ob[(size_t)8 * 512 + col] = r1;
    }
}

// ---------------- layernorm over 512 features ----------------
__global__ __launch_bounds__(128)
void ln512_kernel(const float* __restrict__ X, const float* __restrict__ g,
                  const float* __restrict__ beta, float* __restrict__ Y, int roundOut)
{
    const int row = blockIdx.x;
    const int tid = threadIdx.x;
    const int lane = tid & 31;
    const int wid = tid >> 5;

    float4 v = *(const float4*)&X[(size_t)row * 512 + tid * 4];
    float s  = v.x + v.y + v.z + v.w;
    float sq = v.x * v.x + v.y * v.y + v.z * v.z + v.w * v.w;
#pragma unroll
    for (int o = 16; o; o >>= 1) {
        s  += __shfl_xor_sync(0xffffffffu, s, o);
        sq += __shfl_xor_sync(0xffffffffu, sq, o);
    }
    __shared__ float ws[4], wq[4];
    if (lane == 0) { ws[wid] = s; wq[wid] = sq; }
    __syncthreads();
    float ts = ws[0] + ws[1] + ws[2] + ws[3];
    float tq = wq[0] + wq[1] + wq[2] + wq[3];
    const float mean = ts * (1.f / 512.f);
    const float var  = tq * (1.f / 512.f) - mean * mean;
    const float rstd = rsqrtf(var + 1e-5f);

    float4 gv = *(const float4*)&g[tid * 4];
    float4 bv = *(const float4*)&beta[tid * 4];
    float4 o;
    o.x = (v.x - mean) * rstd * gv.x + bv.x;
    o.y = (v.y - mean) * rstd * gv.y + bv.y;
    o.z = (v.z - mean) * rstd * gv.z + bv.z;
    o.w = (v.w - mean) * rstd * gv.w + bv.w;
    if (roundOut) {
        o.x = round_tf(o.x); o.y = round_tf(o.y);
        o.z = round_tf(o.z); o.w = round_tf(o.w);
    }
    *(float4*)&Y[(size_t)row * 512 + tid * 4] = o;
}

// ---------------- launch ----------------
extern "C" void kernel_launch(void* const* d_in, const int* in_sizes, int n_in,
                              void* d_out, int out_size)
{
    const float* Q   = (const float*)d_in[0];
    const float* K   = (const float*)d_in[1];
    const float* Wq  = (const float*)d_in[2];
    const float* bq  = (const float*)d_in[3];
    const float* Wk  = (const float*)d_in[4];
    const float* bk  = (const float*)d_in[5];
    const float* Wv  = (const float*)d_in[6];
    const float* bv  = (const float*)d_in[7];
    const float* Wo  = (const float*)d_in[8];
    const float* bo  = (const float*)d_in[9];
    const float* g0  = (const float*)d_in[10];
    const float* be0 = (const float*)d_in[11];
    const float* g1  = (const float*)d_in[12];
    const float* be1 = (const float*)d_in[13];
    float* out = (float*)d_out;

    float *Qp, *Kp, *Vt, *Obuf, *Xbuf, *Tbuf;
    cudaGetSymbolAddress((void**)&Qp,   g_Qp);
    cudaGetSymbolAddress((void**)&Kp,   g_Kp);
    cudaGetSymbolAddress((void**)&Vt,   g_Vt);
    cudaGetSymbolAddress((void**)&Obuf, g_O);
    cudaGetSymbolAddress((void**)&Xbuf, g_X);
    cudaGetSymbolAddress((void**)&Tbuf, g_T);

    const int SMEM_ATT = (4 * 64 * KS + 128 * KS) * (int)sizeof(float); // 104448
    cudaFuncSetAttribute(attn_mma3, cudaFuncAttributeMaxDynamicSharedMemorySize, SMEM_ATT);

    dim3 gdim(DV / 128, NROWS / 128);   // (4, 64)
    gemm_tf32<<<gdim, 256>>>(Q, Wq, bq, Qp, NROWS, DV, 512, 0);
    gemm_tf32<<<gdim, 256>>>(K, Wk, bk, Kp, NROWS, DV, 512, 0);
    gemm_tf32<<<gdim, 256>>>(K, Wv, bv, Vt, NROWS, DV, 512, 2);

    dim3 adim(8, 8, 8);                 // (q-tiles of 128, heads, batch)
    attn_mma3<<<adim, 256, SMEM_ATT>>>(Qp, Kp, Vt, Obuf);

    ln512_kernel<<<NROWS, 128>>>(Obuf, g0, be0, Xbuf, 1);
    gemm_tf32<<<gdim, 256>>>(Xbuf, Wo, bo, Tbuf, NROWS, DV, 512, 1);
    ln512_kernel<<<NROWS, 128>>>(Tbuf, g1, be1, out, 0);
}

// round 7
// speedup vs baseline: 2.1264x; 1.1320x over previous
#include <cuda_runtime.h>
#include <cuda_fp16.h>
#include <math.h>
#include <stdint.h>

// ---------------- scratch ----------------
#define NROWS 8192
#define DV    512
__device__ float  g_Qp [NROWS * DV];
__device__ float  g_Kp [NROWS * DV];
__device__ __half g_Vth[NROWS * DV];   // V projected, half, transposed: [b][h][d(64)][key(1024)]
__device__ float  g_O  [NROWS * DV];
__device__ float  g_X  [NROWS * DV];
__device__ float  g_T  [NROWS * DV];

// ---------------- helpers ----------------
__device__ __forceinline__ unsigned f2tf(float x) {
    unsigned r; asm("cvt.rna.tf32.f32 %0, %1;" : "=r"(r) : "f"(x)); return r;
}
__device__ __forceinline__ float round_tf(float x) { return __uint_as_float(f2tf(x)); }
__device__ __forceinline__ unsigned packh2(float lo, float hi) {
    __half2 h = __floats2half2_rn(lo, hi);
    return *reinterpret_cast<unsigned*>(&h);
}
__device__ __forceinline__ void mma8(float* d, const unsigned* a, const unsigned* b) {
    asm volatile(
        "mma.sync.aligned.m16n8k8.row.col.f32.tf32.tf32.f32 "
        "{%0,%1,%2,%3},{%4,%5,%6,%7},{%8,%9},{%0,%1,%2,%3};"
        : "+f"(d[0]), "+f"(d[1]), "+f"(d[2]), "+f"(d[3])
        : "r"(a[0]), "r"(a[1]), "r"(a[2]), "r"(a[3]), "r"(b[0]), "r"(b[1]));
}
__device__ __forceinline__ void mmah16(float* d, const unsigned* a, const unsigned* b) {
    asm volatile(
        "mma.sync.aligned.m16n8k16.row.col.f32.f16.f16.f32 "
        "{%0,%1,%2,%3},{%4,%5,%6,%7},{%8,%9},{%0,%1,%2,%3};"
        : "+f"(d[0]), "+f"(d[1]), "+f"(d[2]), "+f"(d[3])
        : "r"(a[0]), "r"(a[1]), "r"(a[2]), "r"(a[3]), "r"(b[0]), "r"(b[1]));
}
__device__ __forceinline__ void ldsm4(unsigned& r0, unsigned& r1, unsigned& r2, unsigned& r3,
                                      uint32_t addr) {
    asm volatile("ldmatrix.sync.aligned.m8n8.x4.shared.b16 {%0,%1,%2,%3}, [%4];"
                 : "=r"(r0), "=r"(r1), "=r"(r2), "=r"(r3) : "r"(addr));
}
__device__ __forceinline__ void cpa16(uint32_t s, const void* g) {
    asm volatile("cp.async.cg.shared.global [%0], [%1], 16;" :: "r"(s), "l"(g));
}
#define CPA_COMMIT() asm volatile("cp.async.commit_group;")
#define CPA_WAIT(n)  asm volatile("cp.async.wait_group %0;" :: "n"(n))

// ---------------- tf32 GEMM core: 3-stage cp.async pipeline + ldmatrix feed ----------------
// C = A[8192,512] @ W[512,512]^T + bias. mode 0: rna-rounded store; 1: relu+residual(A);
// 2: half store, transposed Vt layout.
#define GP 20
#define GSTG (2 * 128 * GP)      // floats per stage (A then B)
#define GEMM_SMEM (3 * GSTG * 4) // 61440 B

__device__ __forceinline__ void gemm_core(const float* __restrict__ A,
                                          const float* __restrict__ W,
                                          const float* __restrict__ bias,
                                          void* Cv, int mode, float* gsm)
{
    const int tid  = threadIdx.x;
    const int lane = tid & 31;
    const int warp = tid >> 5;
    const int wm = warp & 3;
    const int wn = warp >> 2;
    const int bm = blockIdx.y * 128;
    const int bn = blockIdx.x * 128;
    const int g4 = lane >> 2;
    const int t4 = lane & 3;
    const int i8 = lane & 7;
    const int K = 512, N = 512;

    const uint32_t gsu = (uint32_t)__cvta_generic_to_shared(gsm);
    const uint32_t obA = (uint32_t)(((wm * 32 + ((lane >> 3) & 1) * 8 + i8) * GP
                                     + (lane >> 4) * 4) * 4);
    const uint32_t obB = (uint32_t)((128 * GP + (wn * 64 + (lane >> 4) * 8 + i8) * GP
                                     + ((lane >> 3) & 1) * 4) * 4);

    float acc[2][8][4];
#pragma unroll
    for (int mi = 0; mi < 2; mi++)
#pragma unroll
        for (int ni = 0; ni < 8; ni++)
#pragma unroll
            for (int j = 0; j < 4; j++) acc[mi][ni][j] = 0.f;

    auto issue = [&](int it) {
        const int st = it % 3;
        float* Adst = gsm + st * GSTG;
        float* Bdst = Adst + 128 * GP;
        const int k0 = it * 16;
#pragma unroll
        for (int i = 0; i < 2; i++) {
            const int cid = i * 256 + tid;          // 0..511
            const int row = cid >> 2;
            const int c4  = (cid & 3) * 4;
            cpa16((uint32_t)__cvta_generic_to_shared(Adst + row * GP + c4),
                  &A[(size_t)(bm + row) * K + k0 + c4]);
            cpa16((uint32_t)__cvta_generic_to_shared(Bdst + row * GP + c4),
                  &W[(size_t)(bn + row) * K + k0 + c4]);
        }
    };

    const int NIT = 32;
    issue(0); CPA_COMMIT();
    issue(1); CPA_COMMIT();

    for (int it = 0; it < NIT; it++) {
        if (it + 2 < NIT) issue(it + 2);
        CPA_COMMIT();
        CPA_WAIT(2);
        __syncthreads();

        const uint32_t sb = gsu + (uint32_t)((it % 3) * GSTG * 4);
#pragma unroll
        for (int ks = 0; ks < 2; ks++) {
            unsigned af[2][4];
#pragma unroll
            for (int mi = 0; mi < 2; mi++)
                ldsm4(af[mi][0], af[mi][1], af[mi][2], af[mi][3],
                      sb + obA + (uint32_t)((mi * 16 * GP + ks * 8) * 4));
#pragma unroll
            for (int n2 = 0; n2 < 4; n2++) {
                unsigned b0, b1, b2, b3;
                ldsm4(b0, b1, b2, b3, sb + obB + (uint32_t)((n2 * 16 * GP + ks * 8) * 4));
                unsigned be[2] = {b0, b1}, bo_[2] = {b2, b3};
                mma8(acc[0][n2 * 2],     af[0], be);
                mma8(acc[1][n2 * 2],     af[1], be);
                mma8(acc[0][n2 * 2 + 1], af[0], bo_);
                mma8(acc[1][n2 * 2 + 1], af[1], bo_);
            }
        }
        __syncthreads();
    }

#pragma unroll
    for (int mi = 0; mi < 2; mi++) {
#pragma unroll
        for (int ni = 0; ni < 8; ni++) {
            const int row = bm + wm * 32 + mi * 16 + g4;
            const int col = bn + wn * 64 + ni * 8 + 2 * t4;
            const float b0 = bias[col], b1 = bias[col + 1];
            float v00 = acc[mi][ni][0] + b0, v01 = acc[mi][ni][1] + b1;
            float v10 = acc[mi][ni][2] + b0, v11 = acc[mi][ni][3] + b1;
            if (mode == 2) {
                // half store, transposed: Vt[((b*8+h)*64+d)*1024 + key]
                const int b_ = row >> 10, key = row & 1023;
                const int h_ = col >> 6, d_ = col & 63;
                __half* base = (__half*)Cv + (((size_t)(b_ * 8 + h_) * 64 + d_) << 10);
                base[key]            = __float2half(v00);
                base[1024 + key]     = __float2half(v01);
                base[key + 8]        = __float2half(v10);
                base[1024 + key + 8] = __float2half(v11);
            } else {
                if (mode == 1) {
                    v00 = fmaxf(v00, 0.f) + A[(size_t)row * K + col];
                    v01 = fmaxf(v01, 0.f) + A[(size_t)row * K + col + 1];
                    v10 = fmaxf(v10, 0.f) + A[(size_t)(row + 8) * K + col];
                    v11 = fmaxf(v11, 0.f) + A[(size_t)(row + 8) * K + col + 1];
                } else {
                    v00 = round_tf(v00); v01 = round_tf(v01);
                    v10 = round_tf(v10); v11 = round_tf(v11);
                }
                float* C = (float*)Cv;
                *(float2*)&C[(size_t)row * N + col]       = make_float2(v00, v01);
                *(float2*)&C[(size_t)(row + 8) * N + col] = make_float2(v10, v11);
            }
        }
    }
}

struct PArgs {
    const float* A[3]; const float* W[3]; const float* b[3]; void* C[3];
};

__global__ __launch_bounds__(256) void gemm_proj(PArgs pa) {
    extern __shared__ float gsm[];
    const int z = blockIdx.z;
    gemm_core(pa.A[z], pa.W[z], pa.b[z], pa.C[z], (z == 2) ? 2 : 0, gsm);
}
__global__ __launch_bounds__(256) void gemm_out(const float* __restrict__ A,
                                                const float* __restrict__ W,
                                                const float* __restrict__ b, float* C) {
    extern __shared__ float gsm[];
    gemm_core(A, W, b, C, 1, gsm);
}

// ---------------- flash attention: tf32 S + f16 PV (FA2 fragment reuse), 4-stage cp.async ----------------
// 256 threads = 8 warps; block = (128 q-rows, head, batch); warp owns 16 q rows.
#define KSTR 68   // K tile stride (floats)
#define VSTR 72   // V tile stride (halves) -> 144B rows, conflict-free ldmatrix
#define ATT_SMEM (4 * 64 * KSTR * 4 + 4 * 64 * VSTR * 2)   // 106496 B

__global__ __launch_bounds__(256, 2)
void attn_fa(const float* __restrict__ Qp, const float* __restrict__ Kp,
             const __half* __restrict__ Vth, float* __restrict__ O)
{
    extern __shared__ __align__(16) float dsm[];
    float*  Kst = dsm;                                 // 4 stages x [64][KSTR] f32
    __half* Vst = (__half*)(dsm + 4 * 64 * KSTR);      // 4 stages x [64][VSTR] f16

    const int tid  = threadIdx.x;
    const int lane = tid & 31;
    const int warp = tid >> 5;
    const int g4 = lane >> 2;
    const int t4 = lane & 3;
    const int i8 = lane & 7;

    const int qt = blockIdx.x, h = blockIdx.y, b = blockIdx.z;
    const int q0 = qt * 128;
    const size_t gbase  = ((size_t)b * 1024) * 512 + (size_t)h * 64;
    const size_t vtbase = ((size_t)(b * 8 + h)) << 16;   // halves: *64*1024
    const float scale = 0.044194173824159216f;  // 1/sqrt(512)

    // lane constants
    const uint32_t obB = (uint32_t)((((lane >> 4) * 8 + i8) * KSTR + ((lane >> 3) & 1) * 4) * 4);
    const uint32_t vlane = (uint32_t)(((((lane >> 4) & 1) * 8 + i8) * VSTR
                                      + ((lane >> 3) & 1) * 8) * 2);
    const uint32_t ku0 = (uint32_t)__cvta_generic_to_shared(Kst);
    const uint32_t vu0 = (uint32_t)__cvta_generic_to_shared(Vst);

    auto issue = [&](int kt) {
        const int st = kt & 3;
        float*  kd = Kst + st * 64 * KSTR;
        __half* vd = Vst + st * 64 * VSTR;
#pragma unroll
        for (int i = 0; i < 4; i++) {   // K: 64 rows x 64 f32
            const int cid = i * 256 + tid;
            const int row = cid >> 4;
            const int c4  = (cid & 15) * 4;
            cpa16((uint32_t)__cvta_generic_to_shared(kd + row * KSTR + c4),
                  Kp + gbase + (size_t)(kt * 64 + row) * 512 + c4);
        }
#pragma unroll
        for (int i = 0; i < 2; i++) {   // V: 64 rows(d) x 64 halves
            const int cid = i * 256 + tid;
            const int row = cid >> 3;
            const int c8  = (cid & 7) * 8;
            cpa16((uint32_t)__cvta_generic_to_shared(vd + row * VSTR + c8),
                  Vth + vtbase + (size_t)row * 1024 + kt * 64 + c8);
        }
    };

    // Q fragments (rna tf32, pre-scaled), register-resident
    const int qr = q0 + warp * 16 + g4;
    const float* Qrow0 = Qp + gbase + (size_t)qr * 512;
    const float* Qrow1 = Qrow0 + (size_t)8 * 512;
    unsigned aq[8][4];
#pragma unroll
    for (int ks = 0; ks < 8; ks++) {
        const int c = ks * 8 + t4;
        aq[ks][0] = f2tf(Qrow0[c] * scale);
        aq[ks][1] = f2tf(Qrow1[c] * scale);
        aq[ks][2] = f2tf(Qrow0[c + 4] * scale);
        aq[ks][3] = f2tf(Qrow1[c + 4] * scale);
    }

    float l0 = 0.f, l1 = 0.f;
    float o[8][4];
#pragma unroll
    for (int ni = 0; ni < 8; ni++)
#pragma unroll
        for (int j = 0; j < 4; j++) o[ni][j] = 0.f;

    issue(0); CPA_COMMIT();
    issue(1); CPA_COMMIT();
    issue(2); CPA_COMMIT();

    for (int kt = 0; kt < 16; kt++) {
        if (kt + 3 < 16) issue(kt + 3);
        CPA_COMMIT();
        CPA_WAIT(3);
        __syncthreads();

        const uint32_t ku = ku0 + (uint32_t)((kt & 3) * 64 * KSTR * 4);
        const uint32_t vu = vu0 + (uint32_t)((kt & 3) * 64 * VSTR * 2);

        // S = Qs @ K^T (16 rows x 64 keys per warp), tf32
        float s[8][4];
#pragma unroll
        for (int ni = 0; ni < 8; ni++)
#pragma unroll
            for (int j = 0; j < 4; j++) s[ni][j] = 0.f;

#pragma unroll
        for (int ks = 0; ks < 8; ks++) {
#pragma unroll
            for (int n2 = 0; n2 < 4; n2++) {
                unsigned b0, b1, b2, b3;
                ldsm4(b0, b1, b2, b3, ku + obB + (uint32_t)((n2 * 16 * KSTR + ks * 8) * 4));
                unsigned be[2] = {b0, b1}, bo_[2] = {b2, b3};
                mma8(s[n2 * 2],     aq[ks], be);
                mma8(s[n2 * 2 + 1], aq[ks], bo_);
            }
        }

        // softmax without max subtraction (scores bounded; clamp for safety).
        // partial l per thread (its 16 keys); reduced across t4 lanes after the loop.
#pragma unroll
        for (int ni = 0; ni < 8; ni++) {
            s[ni][0] = __expf(fminf(s[ni][0], 60.f));
            s[ni][1] = __expf(fminf(s[ni][1], 60.f));
            s[ni][2] = __expf(fminf(s[ni][2], 60.f));
            s[ni][3] = __expf(fminf(s[ni][3], 60.f));
            l0 += s[ni][0] + s[ni][1];
            l1 += s[ni][2] + s[ni][3];
        }

        // O += P @ V : P converted f32->f16 IN REGISTERS (C-fragment == f16 A-fragment),
        // V (half, [d][key]) B-fragments via ldmatrix. m16n8k16.
#pragma unroll
        for (int c = 0; c < 4; c++) {
            unsigned ap[4];
            ap[0] = packh2(s[2 * c][0],     s[2 * c][1]);      // row g4,   k 2t4..
            ap[1] = packh2(s[2 * c][2],     s[2 * c][3]);      // row g4+8
            ap[2] = packh2(s[2 * c + 1][0], s[2 * c + 1][1]);  // row g4,   k 2t4+8..
            ap[3] = packh2(s[2 * c + 1][2], s[2 * c + 1][3]);  // row g4+8
#pragma unroll
            for (int n2 = 0; n2 < 4; n2++) {
                unsigned b0, b1, b2, b3;
                ldsm4(b0, b1, b2, b3,
                      vu + vlane + (uint32_t)(((n2 * 16) * VSTR + c * 16) * 2));
                unsigned be[2] = {b0, b1}, bo_[2] = {b2, b3};
                mmah16(o[n2 * 2],     ap, be);
                mmah16(o[n2 * 2 + 1], ap, bo_);
            }
        }
        __syncthreads();
    }

    // reduce softmax denominators across the 4 t4-lanes (full 1024-key sums)
    l0 += __shfl_xor_sync(0xffffffffu, l0, 1);
    l0 += __shfl_xor_sync(0xffffffffu, l0, 2);
    l1 += __shfl_xor_sync(0xffffffffu, l1, 1);
    l1 += __shfl_xor_sync(0xffffffffu, l1, 2);

    // epilogue: normalize + Q residual
    const float inv0 = 1.f / l0, inv1 = 1.f / l1;
    float* Ob = O + gbase + (size_t)qr * 512;
#pragma unroll
    for (int ni = 0; ni < 8; ni++) {
        const int col = ni * 8 + 2 * t4;
        float2 r0 = make_float2(o[ni][0] * inv0 + Qrow0[col],
                                o[ni][1] * inv0 + Qrow0[col + 1]);
        float2 r1 = make_float2(o[ni][2] * inv1 + Qrow1[col],
                                o[ni][3] * inv1 + Qrow1[col + 1]);
        *(float2*)&Ob[col]                   = r0;
        *(float2*)&Ob[(size_t)8 * 512 + col] = r1;
    }
}

// ---------------- layernorm over 512 features ----------------
__global__ __launch_bounds__(128)
void ln512_kernel(const float* __restrict__ X, const float* __restrict__ g,
                  const float* __restrict__ beta, float* __restrict__ Y, int roundOut)
{
    const int row = blockIdx.x;
    const int tid = threadIdx.x;
    const int lane = tid & 31;
    const int wid = tid >> 5;

    float4 v = *(const float4*)&X[(size_t)row * 512 + tid * 4];
    float s  = v.x + v.y + v.z + v.w;
    float sq = v.x * v.x + v.y * v.y + v.z * v.z + v.w * v.w;
#pragma unroll
    for (int o = 16; o; o >>= 1) {
        s  += __shfl_xor_sync(0xffffffffu, s, o);
        sq += __shfl_xor_sync(0xffffffffu, sq, o);
    }
    __shared__ float ws[4], wq[4];
    if (lane == 0) { ws[wid] = s; wq[wid] = sq; }
    __syncthreads();
    float ts = ws[0] + ws[1] + ws[2] + ws[3];
    float tq = wq[0] + wq[1] + wq[2] + wq[3];
    const float mean = ts * (1.f / 512.f);
    const float var  = tq * (1.f / 512.f) - mean * mean;
    const float rstd = rsqrtf(var + 1e-5f);

    float4 gv = *(const float4*)&g[tid * 4];
    float4 bv = *(const float4*)&beta[tid * 4];
    float4 o;
    o.x = (v.x - mean) * rstd * gv.x + bv.x;
    o.y = (v.y - mean) * rstd * gv.y + bv.y;
    o.z = (v.z - mean) * rstd * gv.z + bv.z;
    o.w = (v.w - mean) * rstd * gv.w + bv.w;
    if (roundOut) {
        o.x = round_tf(o.x); o.y = round_tf(o.y);
        o.z = round_tf(o.z); o.w = round_tf(o.w);
    }
    *(float4*)&Y[(size_t)row * 512 + tid * 4] = o;
}

// ---------------- launch ----------------
extern "C" void kernel_launch(void* const* d_in, const int* in_sizes, int n_in,
                              void* d_out, int out_size)
{
    const float* Q   = (const float*)d_in[0];
    const float* K   = (const float*)d_in[1];
    const float* Wq  = (const float*)d_in[2];
    const float* bq  = (const float*)d_in[3];
    const float* Wk  = (const float*)d_in[4];
    const float* bk  = (const float*)d_in[5];
    const float* Wv  = (const float*)d_in[6];
    const float* bv  = (const float*)d_in[7];
    const float* Wo  = (const float*)d_in[8];
    const float* bo  = (const float*)d_in[9];
    const float* g0  = (const float*)d_in[10];
    const float* be0 = (const float*)d_in[11];
    const float* g1  = (const float*)d_in[12];
    const float* be1 = (const float*)d_in[13];
    float* out = (float*)d_out;

    float *Qp, *Kp, *Obuf, *Xbuf, *Tbuf;
    __half* Vth;
    cudaGetSymbolAddress((void**)&Qp,   g_Qp);
    cudaGetSymbolAddress((void**)&Kp,   g_Kp);
    cudaGetSymbolAddress((void**)&Vth,  g_Vth);
    cudaGetSymbolAddress((void**)&Obuf, g_O);
    cudaGetSymbolAddress((void**)&Xbuf, g_X);
    cudaGetSymbolAddress((void**)&Tbuf, g_T);

    cudaFuncSetAttribute(gemm_proj, cudaFuncAttributeMaxDynamicSharedMemorySize, GEMM_SMEM);
    cudaFuncSetAttribute(gemm_out,  cudaFuncAttributeMaxDynamicSharedMemorySize, GEMM_SMEM);
    cudaFuncSetAttribute(attn_fa,   cudaFuncAttributeMaxDynamicSharedMemorySize, ATT_SMEM);

    PArgs pa;
    pa.A[0] = Q;  pa.A[1] = K;  pa.A[2] = K;
    pa.W[0] = Wq; pa.W[1] = Wk; pa.W[2] = Wv;
    pa.b[0] = bq; pa.b[1] = bk; pa.b[2] = bv;
    pa.C[0] = Qp; pa.C[1] = Kp; pa.C[2] = Vth;

    gemm_proj<<<dim3(DV / 128, NROWS / 128, 3), 256, GEMM_SMEM>>>(pa);

    dim3 adim(8, 8, 8);                 // (q-tiles of 128, heads, batch)
    attn_fa<<<adim, 256, ATT_SMEM>>>(Qp, Kp, Vth, Obuf);

    ln512_kernel<<<NROWS, 128>>>(Obuf, g0, be0, Xbuf, 1);
    gemm_out<<<dim3(DV / 128, NROWS / 128), 256, GEMM_SMEM>>>(Xbuf, Wo, bo, Tbuf);
    ln512_kernel<<<NROWS, 128>>>(Tbuf, g1, be1, out, 0);
}